// round 16
// baseline (speedup 1.0000x reference)
#include <cuda_runtime.h>
#include <cuda_fp16.h>
#include <cstdint>

#define N_PTS    32768
#define DIM      256
#define HW       1024
#define CHANS    256
#define ZQ_ELEMS (32 * 256 * 1024)

#define TM       128
#define NTILES   256
#define SB_STAGE 16384
#define SA_BYTES 65536
#define SMEM_MAIN (SA_BYTES + 4 * SB_STAGE)     // 131072

typedef unsigned long long u64;

__device__ uint4 g_A4[NTILES * 4096];      // 16MB pre-swizzled z_hi fp16
__device__ uint4 g_B4[64 * 4 * 1024];      // 4MB  pre-swizzled e_hi fp16
__device__ float g_enorm[8192];
__device__ float g_sz[N_PTS];
__device__ float g_zT[N_PTS * DIM];
__device__ u64   g_cand[N_PTS * 64];       // 16MB packed (b1key|b2key) per slot
__device__ int   g_idx[N_PTS];
__device__ float g_acc;

__device__ __forceinline__ uint32_t smem_u32(const void* p) {
    return (uint32_t)__cvta_generic_to_shared(p);
}
__device__ __forceinline__ void cpasync16(void* dst, const void* src) {
    asm volatile("cp.async.cg.shared.global [%0], [%1], 16;\n"
                 :: "r"(smem_u32(dst)), "l"(src));
}
#define CP_COMMIT() asm volatile("cp.async.commit_group;\n" ::: "memory")
#define CP_WAIT2()  asm volatile("cp.async.wait_group 2;\n" ::: "memory")

__device__ __forceinline__ void ldsm4(uint32_t* r, uint32_t addr) {
    asm volatile("ldmatrix.sync.aligned.m8n8.x4.shared.b16 {%0,%1,%2,%3}, [%4];"
                 : "=r"(r[0]), "=r"(r[1]), "=r"(r[2]), "=r"(r[3]) : "r"(addr));
}
__device__ __forceinline__ void mma16816h(uint32_t* d, const uint32_t* a, const uint32_t* b) {
    asm volatile("mma.sync.aligned.m16n8k16.row.col.f16.f16.f16.f16 "
                 "{%0,%1}, {%2,%3,%4,%5}, {%6,%7}, {%0,%1};"
                 : "+r"(d[0]), "+r"(d[1])
                 : "r"(a[0]), "r"(a[1]), "r"(a[2]), "r"(a[3]), "r"(b[0]), "r"(b[1]));
}
__device__ __forceinline__ uint32_t pack2h(__half a, __half b) {
    return (uint32_t)__half_as_ushort(a) | ((uint32_t)__half_as_ushort(b) << 16);
}
__device__ __forceinline__ uint32_t fkey(float f) {
    uint32_t b = __float_as_uint(f);
    return b ^ ((uint32_t)((int)b >> 31) | 0x80000000u);
}

// ---------- launch 1: fused prep (prep_z | prep_e | zT+sz | enorm) ----------
__global__ void prep_all_kernel(const float* __restrict__ z,
                                const float* __restrict__ e) {
    int bid = blockIdx.x, tid = threadIdx.x;
    if (bid < 256) {
        int t = bid;
        int n0 = t * TM, b = n0 >> 10, hw0 = n0 & 1023;
        const float* zb = z + (size_t)b * CHANS * HW + hw0;
        #pragma unroll
        for (int m = 0; m < 16; ++m) {
            int u = tid + m * 256;
            int p = u & 127, kc = u >> 7;
            __half h[8];
            #pragma unroll
            for (int j = 0; j < 8; ++j)
                h[j] = __float2half_rn(zb[(size_t)(kc * 8 + j) * HW + p]);
            uint4 hx = make_uint4(pack2h(h[0],h[1]), pack2h(h[2],h[3]),
                                  pack2h(h[4],h[5]), pack2h(h[6],h[7]));
            int slot = p * 32 + ((kc & 24) | ((kc ^ (p & 7)) & 7));
            g_A4[(size_t)t * 4096 + slot] = hx;
        }
    } else if (bid < 320) {
        int c = bid - 256;
        #pragma unroll
        for (int m = 0; m < 16; ++m) {
            int u = tid + m * 256;
            int s = u >> 10;
            int w = u & 1023;
            int code = w >> 3, kc = w & 7;
            const float* ep = e + (size_t)(c * 128 + code) * DIM + s * 64 + kc * 8;
            __half h[8];
            #pragma unroll
            for (int j = 0; j < 8; ++j)
                h[j] = __float2half_rn(ep[j] * 8192.0f);
            uint4 x = make_uint4(pack2h(h[0],h[1]), pack2h(h[2],h[3]),
                                 pack2h(h[4],h[5]), pack2h(h[6],h[7]));
            int slot = code * 8 + (kc ^ (code & 7));
            g_B4[((size_t)c * 4 + s) * 1024 + slot] = x;
        }
    } else if (bid < 1344) {
        __shared__ float s_t[256 * 33];
        int n0 = (bid - 320) * 32, b = n0 >> 10, hw0 = n0 & 1023;
        const float* zb = z + (size_t)b * CHANS * HW + hw0;
        #pragma unroll
        for (int m = 0; m < 32; ++m) {
            int c = m * 8 + (tid >> 5), p = tid & 31;
            s_t[c * 33 + p] = zb[(size_t)c * HW + p];
        }
        __syncthreads();
        if (tid < 32) {
            float s = 0.0f;
            #pragma unroll 8
            for (int c = 0; c < 256; ++c) {
                float v = s_t[c * 33 + tid];
                s = __fadd_rn(s, __fmul_rn(v, v));
            }
            g_sz[n0 + tid] = s;
        }
        #pragma unroll
        for (int m = 0; m < 8; ++m) {
            int p = tid >> 3, c0 = (tid & 7) * 4 + m * 32;
            float4 v;
            v.x = s_t[(c0    ) * 33 + p]; v.y = s_t[(c0 + 1) * 33 + p];
            v.z = s_t[(c0 + 2) * 33 + p]; v.w = s_t[(c0 + 3) * 33 + p];
            *(float4*)(g_zT + (size_t)(n0 + p) * DIM + c0) = v;
        }
    } else {
        int lane = tid & 31;
        int gw = (bid - 1344) * 8 + (tid >> 5);
        if (bid == 1344 && tid == 0) g_acc = 0.0f;
        #pragma unroll
        for (int i = 0; i < 4; ++i) {
            int k = gw * 4 + i;
            const float* row = e + (size_t)k * DIM + lane * 8;
            float s = 0.0f;
            #pragma unroll
            for (int j = 0; j < 8; ++j)
                s = __fadd_rn(s, __fmul_rn(row[j], row[j]));
            #pragma unroll
            for (int o = 16; o > 0; o >>= 1)
                s = __fadd_rn(s, __shfl_xor_sync(~0u, s, o));
            if (lane == 0) g_enorm[k] = s;
        }
    }
}

// ---------- launch 2: main GEMM, top-2/thread max-dot epilogue ----------
__global__ void __launch_bounds__(256, 1) vq_main() {
    extern __shared__ __align__(16) char sm[];
    char* sB = sm + SA_BYTES;
    const uint32_t sAu = smem_u32(sm);
    const uint32_t sBu = smem_u32(sB);

    const int tid = threadIdx.x;
    const int wid = tid >> 5, lane = tid & 31;
    const int wm = wid >> 2, wn = wid & 3;
    const int tile = blockIdx.x >> 2, q = blockIdx.x & 3;
    const int n0 = tile * TM;
    const uint4* Bbase = g_B4 + (size_t)q * 64 * 1024;

    {
        const uint4* Asrc = g_A4 + (size_t)tile * 4096;
        uint4* Adst = (uint4*)sm;
        #pragma unroll
        for (int m = 0; m < 16; ++m)
            cpasync16(Adst + tid + m * 256, Asrc + tid + m * 256);
        uint4* bd = (uint4*)sB;
        #pragma unroll
        for (int m = 0; m < 4; ++m) cpasync16(bd + tid + m * 256, Bbase + tid + m * 256);
        CP_COMMIT();
        #pragma unroll
        for (int m = 0; m < 4; ++m) cpasync16(bd + 1024 + tid + m * 256, Bbase + 1024 + tid + m * 256);
        CP_COMMIT();
        #pragma unroll
        for (int m = 0; m < 4; ++m) cpasync16(bd + 2048 + tid + m * 256, Bbase + 2048 + tid + m * 256);
        CP_COMMIT();
    }

    const int lrow = lane >> 2;
    const int lc2  = lane & 3;
    __half bS1[8], bS2[8];
    int    bI1[8], bI2[8];
    #pragma unroll
    for (int i = 0; i < 8; ++i) {
        bS1[i] = __ushort_as_half((unsigned short)0xFC00);  // -inf
        bS2[i] = __ushort_as_half((unsigned short)0xFC00);
        bI1[i] = 0; bI2[i] = 0;
    }

    uint32_t aRow[4], coJ[4];
    {
        int p = (lane & 15);
        int px7 = p & 7;
        #pragma unroll
        for (int mi = 0; mi < 4; ++mi)
            aRow[mi] = (uint32_t)((wm * 64 + mi * 16 + p) * 512);
        const int aCadd = (lane >> 4);
        #pragma unroll
        for (int js = 0; js < 4; ++js)
            coJ[js] = (uint32_t)((((js * 2 + aCadd) ^ px7) & 7) << 4);
    }
    uint32_t boff[2][4];
    {
        int bKadd = (lane >> 3) & 1;
        int c0 = wn * 32 + (lane & 7) + ((lane >> 4) << 3);
        int c1 = c0 + 16;
        #pragma unroll
        for (int js = 0; js < 4; ++js) {
            int kc = js * 2 + bKadd;
            boff[0][js] = (uint32_t)(c0 * 128 + ((kc ^ (c0 & 7)) << 4));
            boff[1][js] = (uint32_t)(c1 * 128 + ((kc ^ (c1 & 7)) << 4));
        }
    }

    uint32_t acc[4][4][2];

    for (int cg = 0; cg < 16; ++cg) {
        #pragma unroll
        for (int mi = 0; mi < 4; ++mi)
            #pragma unroll
            for (int nj = 0; nj < 4; ++nj) {
                acc[mi][nj][0] = 0u; acc[mi][nj][1] = 0u;
            }

        for (int s = 0; s < 4; ++s) {
            const int sidx = cg * 4 + s;
            CP_WAIT2();
            __syncthreads();
            const uint32_t bufb = sBu + (uint32_t)((sidx & 3) * SB_STAGE);
            const uint32_t abase = sAu + (uint32_t)(s * 128);

            #pragma unroll
            for (int js = 0; js < 4; ++js) {
                uint32_t bfr[8];
                ldsm4(bfr,     bufb + boff[0][js]);
                ldsm4(bfr + 4, bufb + boff[1][js]);
                uint32_t a[4][4];
                #pragma unroll
                for (int mi = 0; mi < 4; ++mi)
                    ldsm4(a[mi], abase + aRow[mi] + coJ[js]);
                #pragma unroll
                for (int mi = 0; mi < 4; ++mi) {
                    mma16816h(acc[mi][0], a[mi], bfr);
                    mma16816h(acc[mi][1], a[mi], bfr + 2);
                    mma16816h(acc[mi][2], a[mi], bfr + 4);
                    mma16816h(acc[mi][3], a[mi], bfr + 6);
                }
            }

            const int nx = sidx + 3;
            if (nx < 64) {
                const uint4* src = Bbase + (size_t)nx * 1024;
                uint4* dst = (uint4*)(sB + (nx & 3) * SB_STAGE);
                #pragma unroll
                for (int m = 0; m < 4; ++m)
                    cpasync16(dst + tid + m * 256, src + tid + m * 256);
            }
            CP_COMMIT();
        }

        // epilogue: running top-2 of raw fp16 dot scores per thread
        // (argmax dot == argmin dist up to 7e-8 ||e||^2 spread; exact refine decides)
        const int li0 = cg * 8;
        #pragma unroll
        for (int mi = 0; mi < 4; ++mi)
            #pragma unroll
            for (int nj = 0; nj < 4; ++nj)
                #pragma unroll
                for (int h = 0; h < 2; ++h) {
                    __half2 a2 = *reinterpret_cast<const __half2*>(&acc[mi][nj][h]);
                    int i = mi * 2 + h;
                    __half hx = __low2half(a2), hy = __high2half(a2);
                    if (__hgt(hx, bS2[i])) {
                        if (__hgt(hx, bS1[i])) {
                            bS2[i] = bS1[i]; bI2[i] = bI1[i];
                            bS1[i] = hx; bI1[i] = li0 + nj * 2;
                        } else { bS2[i] = hx; bI2[i] = li0 + nj * 2; }
                    }
                    if (__hgt(hy, bS2[i])) {
                        if (__hgt(hy, bS1[i])) {
                            bS2[i] = bS1[i]; bI2[i] = bI1[i];
                            bS1[i] = hy; bI1[i] = li0 + nj * 2 + 1;
                        } else { bS2[i] = hy; bI2[i] = li0 + nj * 2 + 1; }
                    }
                }
    }

    // one u64 per (point, slot): two u32 keys = fkey(-score) trunc | 7-bit li
    const int slot = q * 16 + wn * 4 + lc2;
    #pragma unroll
    for (int i = 0; i < 8; ++i) {
        int mi = i >> 1, h = i & 1;
        int p = wm * 64 + mi * 16 + lrow + h * 8;
        uint32_t k1 = (fkey(-__half2float(bS1[i])) & 0xFFFFFF80u) | (uint32_t)bI1[i];
        uint32_t k2 = (fkey(-__half2float(bS2[i])) & 0xFFFFFF80u) | (uint32_t)bI2[i];
        g_cand[(size_t)(n0 + p) * 64 + slot] = ((u64)k1 << 32) | k2;
    }
}

// ---------- launch 3: fused select-top8 + exact refine (block per point) ----------
__global__ void selref_kernel(const float* __restrict__ e) {
    __shared__ float s_z[256];
    __shared__ int ssel[8];
    __shared__ u64 sres[8];
    int p = blockIdx.x, tid = threadIdx.x;
    int w = tid >> 5, lane = tid & 31;

    if (w == 0) {
        u64 cand[4];
        #pragma unroll
        for (int j = 0; j < 2; ++j) {
            int s = lane * 2 + j;
            u64 cw = g_cand[(size_t)p * 64 + s];
            int q = s >> 4, wn = (s >> 2) & 3, lc2 = s & 3;
            int base = q * 2048 + wn * 32 + lc2 * 2;
            #pragma unroll
            for (int h = 0; h < 2; ++h) {
                uint32_t k = (h == 0) ? (uint32_t)(cw >> 32) : (uint32_t)cw;
                uint32_t li = k & 127u;
                int gidx = base + (int)(li >> 3) * 128 +
                           (int)((li >> 1) & 3) * 8 + (int)(li & 1);
                cand[j * 2 + h] = ((u64)k << 32) | (unsigned)gidx;
            }
        }
        #pragma unroll 1
        for (int r = 0; r < 8; ++r) {
            u64 m = cand[0];
            if (cand[1] < m) m = cand[1];
            if (cand[2] < m) m = cand[2];
            if (cand[3] < m) m = cand[3];
            #pragma unroll
            for (int o = 16; o > 0; o >>= 1) {
                u64 ww = __shfl_xor_sync(~0u, m, o);
                if (ww < m) m = ww;
            }
            #pragma unroll
            for (int j = 0; j < 4; ++j)
                if (cand[j] == m) cand[j] = ~0ULL;
            if (lane == 0) ssel[r] = (int)((unsigned)m & 8191u);
        }
    } else if (w == 1) {
        float4* z4 = (float4*)s_z;
        const float4* src = (const float4*)(g_zT + (size_t)p * DIM);
        z4[lane] = src[lane];
        z4[lane + 32] = src[lane + 32];
    }
    __syncthreads();

    int k = ssel[w];
    float4 za = *(const float4*)(s_z + lane * 8);
    float4 zb = *(const float4*)(s_z + lane * 8 + 4);
    const float* er = e + (size_t)k * DIM + lane * 8;
    float4 ea = *(const float4*)er;
    float4 eb = *(const float4*)(er + 4);
    float s = 0.0f;
    s = __fadd_rn(s, __fmul_rn(za.x, ea.x));
    s = __fadd_rn(s, __fmul_rn(za.y, ea.y));
    s = __fadd_rn(s, __fmul_rn(za.z, ea.z));
    s = __fadd_rn(s, __fmul_rn(za.w, ea.w));
    s = __fadd_rn(s, __fmul_rn(zb.x, eb.x));
    s = __fadd_rn(s, __fmul_rn(zb.y, eb.y));
    s = __fadd_rn(s, __fmul_rn(zb.z, eb.z));
    s = __fadd_rn(s, __fmul_rn(zb.w, eb.w));
    #pragma unroll
    for (int o = 16; o > 0; o >>= 1)
        s = __fadd_rn(s, __shfl_xor_sync(~0u, s, o));
    float d = __fadd_rn(__fadd_rn(g_sz[p], g_enorm[k]), __fmul_rn(s, -2.0f));
    if (lane == 0)
        sres[w] = ((u64)__float_as_uint(d) << 32) | (unsigned)k;
    __syncthreads();
    if (tid == 0) {
        u64 m = sres[0];
        #pragma unroll
        for (int j = 1; j < 8; ++j)
            if (sres[j] < m) m = sres[j];
        g_idx[p] = (int)(unsigned)m;
    }
}

// ---------- launch 4: z_q + MSE, channel-quartered (grid 1024) ----------
__global__ void write_out3(const float* __restrict__ z,
                           const float* __restrict__ e,
                           float* __restrict__ out) {
    __shared__ float se[128 * 65];
    __shared__ int sidx[128];
    __shared__ float ws[8];
    int blk = blockIdx.x, tid = threadIdx.x;
    int b   = blk >> 5;
    int hwq = (blk >> 2) & 7;
    int cq  = blk & 3;
    int hw0 = hwq * 128, ch0 = cq * 64;

    if (tid < 128) sidx[tid] = g_idx[b * 1024 + hw0 + tid];
    __syncthreads();
    #pragma unroll
    for (int m = 0; m < 8; ++m) {
        int i = tid + m * 256;
        int r = i >> 4, f4 = i & 15;
        float4 v = *(const float4*)(e + (size_t)sidx[r] * DIM + ch0 + f4 * 4);
        float* srow = se + r * 65 + f4 * 4;
        srow[0] = v.x; srow[1] = v.y; srow[2] = v.z; srow[3] = v.w;
    }
    __syncthreads();

    int p = tid & 127, chh = tid >> 7;
    const float* zb = z + (size_t)b * CHANS * HW + hw0 + p;
    float* ob = out + (size_t)b * CHANS * HW + hw0 + p;
    float local = 0.0f;
    #pragma unroll 4
    for (int it = 0; it < 32; ++it) {
        int cl = it * 2 + chh;
        int c = ch0 + cl;
        float zv = zb[(size_t)c * HW];
        float dq = __fsub_rn(se[p * 65 + cl], zv);
        ob[(size_t)c * HW] = __fadd_rn(zv, dq);
        local = __fadd_rn(local, __fmul_rn(dq, dq));
    }
    #pragma unroll
    for (int o = 16; o > 0; o >>= 1) local += __shfl_xor_sync(~0u, local, o);
    int lane = tid & 31, wd = tid >> 5;
    if (lane == 0) ws[wd] = local;
    __syncthreads();
    if (wd == 0) {
        float v = (lane < 8) ? ws[lane] : 0.0f;
        #pragma unroll
        for (int o = 4; o > 0; o >>= 1) v += __shfl_xor_sync(~0u, v, o);
        if (lane == 0) atomicAdd(&g_acc, v);
    }
}

// ---------- launch 5: scalars + indices ----------
__global__ void finalize_kernel(float* __restrict__ out, int out_size) {
    int t = blockIdx.x * blockDim.x + threadIdx.x;
    if (t < N_PTS) {
        int o = ZQ_ELEMS + 3 + t;
        if (o < out_size) out[o] = (float)g_idx[t];
    }
    if (t == 0) {
        float mse  = g_acc * (1.0f / (float)ZQ_ELEMS);
        float comm = 0.25f * mse;
        if (ZQ_ELEMS + 0 < out_size) out[ZQ_ELEMS + 0] = __fadd_rn(comm, mse);
        if (ZQ_ELEMS + 1 < out_size) out[ZQ_ELEMS + 1] = comm;
        if (ZQ_ELEMS + 2 < out_size) out[ZQ_ELEMS + 2] = mse;
    }
}

extern "C" void kernel_launch(void* const* d_in, const int* in_sizes, int n_in,
                              void* d_out, int out_size) {
    const float* z = (const float*)d_in[0];
    const float* e = (const float*)d_in[1];
    float* out = (float*)d_out;
    cudaFuncSetAttribute(vq_main, cudaFuncAttributeMaxDynamicSharedMemorySize, SMEM_MAIN);
    prep_all_kernel<<<1600, 256>>>(z, e);
    vq_main<<<1024, 256, SMEM_MAIN>>>();
    selref_kernel<<<N_PTS, 256>>>(e);
    write_out3<<<1024, 256>>>(z, e, out);
    finalize_kernel<<<(N_PTS + 255) / 256, 256>>>(out, out_size);
}

// round 17
// speedup vs baseline: 1.0684x; 1.0684x over previous
#include <cuda_runtime.h>
#include <cuda_fp16.h>
#include <cstdint>

#define N_PTS    32768
#define DIM      256
#define HW       1024
#define CHANS    256
#define ZQ_ELEMS (32 * 256 * 1024)

#define TM       128
#define NTILES   256
#define SB_STAGE 16384
#define SA_BYTES 65536
#define SMEM_MAIN (SA_BYTES + 4 * SB_STAGE)     // 131072

typedef unsigned long long u64;

__device__ uint4 g_A4[NTILES * 4096];      // 16MB pre-swizzled z_hi fp16
__device__ uint4 g_B4[64 * 4 * 1024];      // 4MB  pre-swizzled e_hi fp16
__device__ float g_enorm[8192];
__device__ float g_sz[N_PTS];
__device__ float g_zT[N_PTS * DIM];
__device__ u64   g_cand[N_PTS * 64];       // 16MB packed (k1|k2) per slot
__device__ int   g_idx[N_PTS];
__device__ float g_acc;

__device__ __forceinline__ uint32_t smem_u32(const void* p) {
    return (uint32_t)__cvta_generic_to_shared(p);
}
__device__ __forceinline__ void cpasync16(void* dst, const void* src) {
    asm volatile("cp.async.cg.shared.global [%0], [%1], 16;\n"
                 :: "r"(smem_u32(dst)), "l"(src));
}
#define CP_COMMIT() asm volatile("cp.async.commit_group;\n" ::: "memory")
#define CP_WAIT2()  asm volatile("cp.async.wait_group 2;\n" ::: "memory")

__device__ __forceinline__ void ldsm4(uint32_t* r, uint32_t addr) {
    asm volatile("ldmatrix.sync.aligned.m8n8.x4.shared.b16 {%0,%1,%2,%3}, [%4];"
                 : "=r"(r[0]), "=r"(r[1]), "=r"(r[2]), "=r"(r[3]) : "r"(addr));
}
__device__ __forceinline__ void mma16816h(uint32_t* d, const uint32_t* a, const uint32_t* b) {
    asm volatile("mma.sync.aligned.m16n8k16.row.col.f16.f16.f16.f16 "
                 "{%0,%1}, {%2,%3,%4,%5}, {%6,%7}, {%0,%1};"
                 : "+r"(d[0]), "+r"(d[1])
                 : "r"(a[0]), "r"(a[1]), "r"(a[2]), "r"(a[3]), "r"(b[0]), "r"(b[1]));
}
__device__ __forceinline__ uint32_t pack2h(__half a, __half b) {
    return (uint32_t)__half_as_ushort(a) | ((uint32_t)__half_as_ushort(b) << 16);
}
__device__ __forceinline__ uint32_t fkey(float f) {
    uint32_t b = __float_as_uint(f);
    return b ^ ((uint32_t)((int)b >> 31) | 0x80000000u);
}

// ---------- launch 1: fused prep (prep_z | prep_e | zT+sz | enorm) ----------
__global__ void prep_all_kernel(const float* __restrict__ z,
                                const float* __restrict__ e) {
    int bid = blockIdx.x, tid = threadIdx.x;
    if (bid < 256) {
        int t = bid;
        int n0 = t * TM, b = n0 >> 10, hw0 = n0 & 1023;
        const float* zb = z + (size_t)b * CHANS * HW + hw0;
        #pragma unroll
        for (int m = 0; m < 16; ++m) {
            int u = tid + m * 256;
            int p = u & 127, kc = u >> 7;
            __half h[8];
            #pragma unroll
            for (int j = 0; j < 8; ++j)
                h[j] = __float2half_rn(zb[(size_t)(kc * 8 + j) * HW + p]);
            uint4 hx = make_uint4(pack2h(h[0],h[1]), pack2h(h[2],h[3]),
                                  pack2h(h[4],h[5]), pack2h(h[6],h[7]));
            int slot = p * 32 + ((kc & 24) | ((kc ^ (p & 7)) & 7));
            g_A4[(size_t)t * 4096 + slot] = hx;
        }
    } else if (bid < 320) {
        int c = bid - 256;
        #pragma unroll
        for (int m = 0; m < 16; ++m) {
            int u = tid + m * 256;
            int s = u >> 10;
            int w = u & 1023;
            int code = w >> 3, kc = w & 7;
            const float* ep = e + (size_t)(c * 128 + code) * DIM + s * 64 + kc * 8;
            __half h[8];
            #pragma unroll
            for (int j = 0; j < 8; ++j)
                h[j] = __float2half_rn(ep[j] * 8192.0f);
            uint4 x = make_uint4(pack2h(h[0],h[1]), pack2h(h[2],h[3]),
                                 pack2h(h[4],h[5]), pack2h(h[6],h[7]));
            int slot = code * 8 + (kc ^ (code & 7));
            g_B4[((size_t)c * 4 + s) * 1024 + slot] = x;
        }
    } else if (bid < 1344) {
        __shared__ float s_t[256 * 33];
        int n0 = (bid - 320) * 32, b = n0 >> 10, hw0 = n0 & 1023;
        const float* zb = z + (size_t)b * CHANS * HW + hw0;
        #pragma unroll
        for (int m = 0; m < 32; ++m) {
            int c = m * 8 + (tid >> 5), p = tid & 31;
            s_t[c * 33 + p] = zb[(size_t)c * HW + p];
        }
        __syncthreads();
        if (tid < 32) {
            float s = 0.0f;
            #pragma unroll 8
            for (int c = 0; c < 256; ++c) {
                float v = s_t[c * 33 + tid];
                s = __fadd_rn(s, __fmul_rn(v, v));
            }
            g_sz[n0 + tid] = s;
        }
        #pragma unroll
        for (int m = 0; m < 8; ++m) {
            int p = tid >> 3, c0 = (tid & 7) * 4 + m * 32;
            float4 v;
            v.x = s_t[(c0    ) * 33 + p]; v.y = s_t[(c0 + 1) * 33 + p];
            v.z = s_t[(c0 + 2) * 33 + p]; v.w = s_t[(c0 + 3) * 33 + p];
            *(float4*)(g_zT + (size_t)(n0 + p) * DIM + c0) = v;
        }
    } else {
        int lane = tid & 31;
        int gw = (bid - 1344) * 8 + (tid >> 5);
        if (bid == 1344 && tid == 0) g_acc = 0.0f;
        #pragma unroll
        for (int i = 0; i < 4; ++i) {
            int k = gw * 4 + i;
            const float* row = e + (size_t)k * DIM + lane * 8;
            float s = 0.0f;
            #pragma unroll
            for (int j = 0; j < 8; ++j)
                s = __fadd_rn(s, __fmul_rn(row[j], row[j]));
            #pragma unroll
            for (int o = 16; o > 0; o >>= 1)
                s = __fadd_rn(s, __shfl_xor_sync(~0u, s, o));
            if (lane == 0) g_enorm[k] = s;
        }
    }
}

// ---------- launch 2: main GEMM, float-compare top-2 max-dot epilogue ----------
__global__ void __launch_bounds__(256, 1) vq_main() {
    extern __shared__ __align__(16) char sm[];
    char* sB = sm + SA_BYTES;
    const uint32_t sAu = smem_u32(sm);
    const uint32_t sBu = smem_u32(sB);

    const int tid = threadIdx.x;
    const int wid = tid >> 5, lane = tid & 31;
    const int wm = wid >> 2, wn = wid & 3;
    const int tile = blockIdx.x >> 2, q = blockIdx.x & 3;
    const int n0 = tile * TM;
    const uint4* Bbase = g_B4 + (size_t)q * 64 * 1024;

    {
        const uint4* Asrc = g_A4 + (size_t)tile * 4096;
        uint4* Adst = (uint4*)sm;
        #pragma unroll
        for (int m = 0; m < 16; ++m)
            cpasync16(Adst + tid + m * 256, Asrc + tid + m * 256);
        uint4* bd = (uint4*)sB;
        #pragma unroll
        for (int m = 0; m < 4; ++m) cpasync16(bd + tid + m * 256, Bbase + tid + m * 256);
        CP_COMMIT();
        #pragma unroll
        for (int m = 0; m < 4; ++m) cpasync16(bd + 1024 + tid + m * 256, Bbase + 1024 + tid + m * 256);
        CP_COMMIT();
        #pragma unroll
        for (int m = 0; m < 4; ++m) cpasync16(bd + 2048 + tid + m * 256, Bbase + 2048 + tid + m * 256);
        CP_COMMIT();
    }

    const int lrow = lane >> 2;
    const int lc2  = lane & 3;
    float b1[8], b2[8];
    int   i1[8], i2[8];
    #pragma unroll
    for (int i = 0; i < 8; ++i) {
        b1[i] = -3.4e38f; b2[i] = -3.4e38f; i1[i] = 0; i2[i] = 0;
    }

    uint32_t aRow[4], coJ[4];
    {
        int p = (lane & 15);
        int px7 = p & 7;
        #pragma unroll
        for (int mi = 0; mi < 4; ++mi)
            aRow[mi] = (uint32_t)((wm * 64 + mi * 16 + p) * 512);
        const int aCadd = (lane >> 4);
        #pragma unroll
        for (int js = 0; js < 4; ++js)
            coJ[js] = (uint32_t)((((js * 2 + aCadd) ^ px7) & 7) << 4);
    }
    uint32_t boff[2][4];
    {
        int bKadd = (lane >> 3) & 1;
        int c0 = wn * 32 + (lane & 7) + ((lane >> 4) << 3);
        int c1 = c0 + 16;
        #pragma unroll
        for (int js = 0; js < 4; ++js) {
            int kc = js * 2 + bKadd;
            boff[0][js] = (uint32_t)(c0 * 128 + ((kc ^ (c0 & 7)) << 4));
            boff[1][js] = (uint32_t)(c1 * 128 + ((kc ^ (c1 & 7)) << 4));
        }
    }

    uint32_t acc[4][4][2];

    for (int cg = 0; cg < 16; ++cg) {
        #pragma unroll
        for (int mi = 0; mi < 4; ++mi)
            #pragma unroll
            for (int nj = 0; nj < 4; ++nj) {
                acc[mi][nj][0] = 0u; acc[mi][nj][1] = 0u;
            }

        for (int s = 0; s < 4; ++s) {
            const int sidx = cg * 4 + s;
            CP_WAIT2();
            __syncthreads();
            const uint32_t bufb = sBu + (uint32_t)((sidx & 3) * SB_STAGE);
            const uint32_t abase = sAu + (uint32_t)(s * 128);

            #pragma unroll
            for (int js = 0; js < 4; ++js) {
                uint32_t bfr[8];
                ldsm4(bfr,     bufb + boff[0][js]);
                ldsm4(bfr + 4, bufb + boff[1][js]);
                uint32_t a[4][4];
                #pragma unroll
                for (int mi = 0; mi < 4; ++mi)
                    ldsm4(a[mi], abase + aRow[mi] + coJ[js]);
                #pragma unroll
                for (int mi = 0; mi < 4; ++mi) {
                    mma16816h(acc[mi][0], a[mi], bfr);
                    mma16816h(acc[mi][1], a[mi], bfr + 2);
                    mma16816h(acc[mi][2], a[mi], bfr + 4);
                    mma16816h(acc[mi][3], a[mi], bfr + 6);
                }
            }

            const int nx = sidx + 3;
            if (nx < 64) {
                const uint4* src = Bbase + (size_t)nx * 1024;
                uint4* dst = (uint4*)(sB + (nx & 3) * SB_STAGE);
                #pragma unroll
                for (int m = 0; m < 4; ++m)
                    cpasync16(dst + tid + m * 256, src + tid + m * 256);
            }
            CP_COMMIT();
        }

        // epilogue: float-compare top-2 of raw dot scores (bigger = closer;
        // ||e||^2 spread 7e-8 << fp16-acc noise, exact refine decides)
        const int li0 = cg * 8;
        #pragma unroll
        for (int mi = 0; mi < 4; ++mi)
            #pragma unroll
            for (int nj = 0; nj < 4; ++nj)
                #pragma unroll
                for (int h = 0; h < 2; ++h) {
                    float2 f = __half22float2(
                        *reinterpret_cast<const __half2*>(&acc[mi][nj][h]));
                    int i = mi * 2 + h;
                    int idx0 = li0 + nj * 2;
                    if (f.x > b2[i]) {
                        if (f.x > b1[i]) { b2[i] = b1[i]; i2[i] = i1[i]; b1[i] = f.x; i1[i] = idx0; }
                        else             { b2[i] = f.x; i2[i] = idx0; }
                    }
                    if (f.y > b2[i]) {
                        if (f.y > b1[i]) { b2[i] = b1[i]; i2[i] = i1[i]; b1[i] = f.y; i1[i] = idx0 + 1; }
                        else             { b2[i] = f.y; i2[i] = idx0 + 1; }
                    }
                }
    }

    // one u64 per (point, slot): two u32 keys = fkey(-score) trunc | 7-bit li
    const int slot = q * 16 + wn * 4 + lc2;
    #pragma unroll
    for (int i = 0; i < 8; ++i) {
        int mi = i >> 1, h = i & 1;
        int p = wm * 64 + mi * 16 + lrow + h * 8;
        uint32_t k1 = (fkey(-b1[i]) & 0xFFFFFF80u) | (uint32_t)i1[i];
        uint32_t k2 = (fkey(-b2[i]) & 0xFFFFFF80u) | (uint32_t)i2[i];
        g_cand[(size_t)(n0 + p) * 64 + slot] = ((u64)k1 << 32) | k2;
    }
}

// ---------- launch 3: fused select-top8 + exact refine (block per point) ----------
__global__ void selref_kernel(const float* __restrict__ e) {
    __shared__ float s_z[256];
    __shared__ int ssel[8];
    __shared__ u64 sres[8];
    int p = blockIdx.x, tid = threadIdx.x;
    int w = tid >> 5, lane = tid & 31;

    if (w == 0) {
        u64 cand[4];
        #pragma unroll
        for (int j = 0; j < 2; ++j) {
            int s = lane * 2 + j;
            u64 cw = g_cand[(size_t)p * 64 + s];
            int q = s >> 4, wn = (s >> 2) & 3, lc2 = s & 3;
            int base = q * 2048 + wn * 32 + lc2 * 2;
            #pragma unroll
            for (int h = 0; h < 2; ++h) {
                uint32_t k = (h == 0) ? (uint32_t)(cw >> 32) : (uint32_t)cw;
                uint32_t li = k & 127u;
                int gidx = base + (int)(li >> 3) * 128 +
                           (int)((li >> 1) & 3) * 8 + (int)(li & 1);
                cand[j * 2 + h] = ((u64)k << 32) | (unsigned)gidx;
            }
        }
        #pragma unroll 1
        for (int r = 0; r < 8; ++r) {
            u64 m = cand[0];
            if (cand[1] < m) m = cand[1];
            if (cand[2] < m) m = cand[2];
            if (cand[3] < m) m = cand[3];
            #pragma unroll
            for (int o = 16; o > 0; o >>= 1) {
                u64 ww = __shfl_xor_sync(~0u, m, o);
                if (ww < m) m = ww;
            }
            #pragma unroll
            for (int j = 0; j < 4; ++j)
                if (cand[j] == m) cand[j] = ~0ULL;
            if (lane == 0) ssel[r] = (int)((unsigned)m & 8191u);
        }
    } else if (w == 1) {
        float4* z4 = (float4*)s_z;
        const float4* src = (const float4*)(g_zT + (size_t)p * DIM);
        z4[lane] = src[lane];
        z4[lane + 32] = src[lane + 32];
    }
    __syncthreads();

    int k = ssel[w];
    float4 za = *(const float4*)(s_z + lane * 8);
    float4 zb = *(const float4*)(s_z + lane * 8 + 4);
    const float* er = e + (size_t)k * DIM + lane * 8;
    float4 ea = *(const float4*)er;
    float4 eb = *(const float4*)(er + 4);
    float s = 0.0f;
    s = __fadd_rn(s, __fmul_rn(za.x, ea.x));
    s = __fadd_rn(s, __fmul_rn(za.y, ea.y));
    s = __fadd_rn(s, __fmul_rn(za.z, ea.z));
    s = __fadd_rn(s, __fmul_rn(za.w, ea.w));
    s = __fadd_rn(s, __fmul_rn(zb.x, eb.x));
    s = __fadd_rn(s, __fmul_rn(zb.y, eb.y));
    s = __fadd_rn(s, __fmul_rn(zb.z, eb.z));
    s = __fadd_rn(s, __fmul_rn(zb.w, eb.w));
    #pragma unroll
    for (int o = 16; o > 0; o >>= 1)
        s = __fadd_rn(s, __shfl_xor_sync(~0u, s, o));
    float d = __fadd_rn(__fadd_rn(g_sz[p], g_enorm[k]), __fmul_rn(s, -2.0f));
    if (lane == 0)
        sres[w] = ((u64)__float_as_uint(d) << 32) | (unsigned)k;
    __syncthreads();
    if (tid == 0) {
        u64 m = sres[0];
        #pragma unroll
        for (int j = 1; j < 8; ++j)
            if (sres[j] < m) m = sres[j];
        g_idx[p] = (int)(unsigned)m;
    }
}

// ---------- launch 4: z_q + MSE, channel-quartered (grid 1024) ----------
__global__ void write_out3(const float* __restrict__ z,
                           const float* __restrict__ e,
                           float* __restrict__ out) {
    __shared__ float se[128 * 65];
    __shared__ int sidx[128];
    __shared__ float ws[8];
    int blk = blockIdx.x, tid = threadIdx.x;
    int b   = blk >> 5;
    int hwq = (blk >> 2) & 7;
    int cq  = blk & 3;
    int hw0 = hwq * 128, ch0 = cq * 64;

    if (tid < 128) sidx[tid] = g_idx[b * 1024 + hw0 + tid];
    __syncthreads();
    #pragma unroll
    for (int m = 0; m < 8; ++m) {
        int i = tid + m * 256;
        int r = i >> 4, f4 = i & 15;
        float4 v = *(const float4*)(e + (size_t)sidx[r] * DIM + ch0 + f4 * 4);
        float* srow = se + r * 65 + f4 * 4;
        srow[0] = v.x; srow[1] = v.y; srow[2] = v.z; srow[3] = v.w;
    }
    __syncthreads();

    int p = tid & 127, chh = tid >> 7;
    const float* zb = z + (size_t)b * CHANS * HW + hw0 + p;
    float* ob = out + (size_t)b * CHANS * HW + hw0 + p;
    float local = 0.0f;
    #pragma unroll 4
    for (int it = 0; it < 32; ++it) {
        int cl = it * 2 + chh;
        int c = ch0 + cl;
        float zv = zb[(size_t)c * HW];
        float dq = __fsub_rn(se[p * 65 + cl], zv);
        ob[(size_t)c * HW] = __fadd_rn(zv, dq);
        local = __fadd_rn(local, __fmul_rn(dq, dq));
    }
    #pragma unroll
    for (int o = 16; o > 0; o >>= 1) local += __shfl_xor_sync(~0u, local, o);
    int lane = tid & 31, wd = tid >> 5;
    if (lane == 0) ws[wd] = local;
    __syncthreads();
    if (wd == 0) {
        float v = (lane < 8) ? ws[lane] : 0.0f;
        #pragma unroll
        for (int o = 4; o > 0; o >>= 1) v += __shfl_xor_sync(~0u, v, o);
        if (lane == 0) atomicAdd(&g_acc, v);
    }
}

// ---------- launch 5: scalars + indices ----------
__global__ void finalize_kernel(float* __restrict__ out, int out_size) {
    int t = blockIdx.x * blockDim.x + threadIdx.x;
    if (t < N_PTS) {
        int o = ZQ_ELEMS + 3 + t;
        if (o < out_size) out[o] = (float)g_idx[t];
    }
    if (t == 0) {
        float mse  = g_acc * (1.0f / (float)ZQ_ELEMS);
        float comm = 0.25f * mse;
        if (ZQ_ELEMS + 0 < out_size) out[ZQ_ELEMS + 0] = __fadd_rn(comm, mse);
        if (ZQ_ELEMS + 1 < out_size) out[ZQ_ELEMS + 1] = comm;
        if (ZQ_ELEMS + 2 < out_size) out[ZQ_ELEMS + 2] = mse;
    }
}

extern "C" void kernel_launch(void* const* d_in, const int* in_sizes, int n_in,
                              void* d_out, int out_size) {
    const float* z = (const float*)d_in[0];
    const float* e = (const float*)d_in[1];
    float* out = (float*)d_out;
    cudaFuncSetAttribute(vq_main, cudaFuncAttributeMaxDynamicSharedMemorySize, SMEM_MAIN);
    prep_all_kernel<<<1600, 256>>>(z, e);
    vq_main<<<1024, 256, SMEM_MAIN>>>();
    selref_kernel<<<N_PTS, 256>>>(e);
    write_out3<<<1024, 256>>>(z, e, out);
    finalize_kernel<<<(N_PTS + 255) / 256, 256>>>(out, out_size);
}